// round 4
// baseline (speedup 1.0000x reference)
#include <cuda_runtime.h>
#include <math.h>

#define B_DIM   4096
#define ZDIM    128
#define IN_DIM  512
#define H_DIM   1024
#define SEQ_LEN 12

#define BM 128
#define BN 128
#define BK 16
#define PAD 4

// Scratch (allocation-free rule: __device__ globals)
__device__ float g_x0[B_DIM * IN_DIM];     // 8 MB
__device__ float g_state[B_DIM * H_DIM];   // 16 MB
__device__ float g_spre[B_DIM * H_DIM];    // 16 MB
__device__ float g_u[B_DIM * H_DIM];       // 16 MB
__device__ float g_rs[B_DIM * H_DIM];      // 16 MB

enum { EPI_LIN = 0, EPI_BELTA = 1, EPI_SIGU = 2, EPI_SIGR = 3, EPI_NEW = 4 };

__global__ void zero_kernel(float* __restrict__ p, int n) {
    int i = blockIdx.x * blockDim.x + threadIdx.x;
    if (i < n) p[i] = 0.0f;
}

__device__ __forceinline__ float4 ldA(const float* __restrict__ A1, int lda1, int K1,
                                      const float* __restrict__ A2, int lda2,
                                      int m, int k) {
    // Tile never straddles K1 boundary (BK divides K1), so branch is warp-uniform.
    if (k < K1) return *(const float4*)(A1 + (size_t)m * lda1 + k);
    return *(const float4*)(A2 + (size_t)m * lda2 + (k - K1));
}

// C[M,N] = epi( [A1 | A2] @ W + bias ),  W is (K1+K2, N) row-major.
template <int EPI>
__global__ __launch_bounds__(256, 2)
void gemm_epi(const float* __restrict__ A1, int lda1, int K1,
              const float* __restrict__ A2, int lda2, int K2,
              const float* __restrict__ W,
              const float* __restrict__ bias,
              const float* __restrict__ ex1,   // BELTA: state | SIGR: spre | NEW: u
              const float* __restrict__ ex2,   // NEW: spre
              float* __restrict__ C, int ldc, int N)
{
    __shared__ float As[2][BK][BM + PAD];
    __shared__ float Bs[2][BK][BN];

    const int tid = threadIdx.x;
    const int tx = tid & 15;          // 0..15 -> 8 cols each
    const int ty = tid >> 4;          // 0..15 -> 8 rows each
    const int bm = blockIdx.y * BM;
    const int bn = blockIdx.x * BN;

    const int KT = (K1 + K2) / BK;

    // A-tile loader mapping: 2 float4 per thread
    const int ar0 = tid >> 2;                  // 0..63
    const int ac0 = (tid & 3) * 4;             // 0,4,8,12
    // B-tile loader mapping: 2 float4 per thread
    const int br0 = tid >> 5;                  // 0..7
    const int bc0 = (tid & 31) * 4;            // 0..124

    float acc[8][8];
#pragma unroll
    for (int i = 0; i < 8; i++)
#pragma unroll
        for (int j = 0; j < 8; j++) acc[i][j] = 0.0f;

    // ---- prologue: load tile 0 into buffer 0 ----
    {
        float4 a0 = ldA(A1, lda1, K1, A2, lda2, bm + ar0,      ac0);
        float4 a1 = ldA(A1, lda1, K1, A2, lda2, bm + ar0 + 64, ac0);
        float4 b0 = *(const float4*)(W + (size_t)(br0)*N + bn + bc0);
        float4 b1 = *(const float4*)(W + (size_t)(br0 + 8) * N + bn + bc0);
        As[0][ac0 + 0][ar0] = a0.x; As[0][ac0 + 1][ar0] = a0.y;
        As[0][ac0 + 2][ar0] = a0.z; As[0][ac0 + 3][ar0] = a0.w;
        As[0][ac0 + 0][ar0 + 64] = a1.x; As[0][ac0 + 1][ar0 + 64] = a1.y;
        As[0][ac0 + 2][ar0 + 64] = a1.z; As[0][ac0 + 3][ar0 + 64] = a1.w;
        *(float4*)&Bs[0][br0][bc0]     = b0;
        *(float4*)&Bs[0][br0 + 8][bc0] = b1;
    }
    __syncthreads();

    for (int kt = 0; kt < KT; kt++) {
        const int buf = kt & 1;
        float4 a0n, a1n, b0n, b1n;
        const bool more = (kt + 1 < KT);
        if (more) {
            const int ks = (kt + 1) * BK;
            a0n = ldA(A1, lda1, K1, A2, lda2, bm + ar0,      ks + ac0);
            a1n = ldA(A1, lda1, K1, A2, lda2, bm + ar0 + 64, ks + ac0);
            b0n = *(const float4*)(W + (size_t)(ks + br0) * N + bn + bc0);
            b1n = *(const float4*)(W + (size_t)(ks + br0 + 8) * N + bn + bc0);
        }

#pragma unroll
        for (int k = 0; k < BK; k++) {
            float a[8], b[8];
            *(float4*)&a[0] = *(const float4*)&As[buf][k][ty * 8];
            *(float4*)&a[4] = *(const float4*)&As[buf][k][ty * 8 + 4];
            *(float4*)&b[0] = *(const float4*)&Bs[buf][k][tx * 8];
            *(float4*)&b[4] = *(const float4*)&Bs[buf][k][tx * 8 + 4];
#pragma unroll
            for (int i = 0; i < 8; i++)
#pragma unroll
                for (int j = 0; j < 8; j++)
                    acc[i][j] = fmaf(a[i], b[j], acc[i][j]);
        }

        if (more) {
            const int nb = buf ^ 1;
            As[nb][ac0 + 0][ar0] = a0n.x; As[nb][ac0 + 1][ar0] = a0n.y;
            As[nb][ac0 + 2][ar0] = a0n.z; As[nb][ac0 + 3][ar0] = a0n.w;
            As[nb][ac0 + 0][ar0 + 64] = a1n.x; As[nb][ac0 + 1][ar0 + 64] = a1n.y;
            As[nb][ac0 + 2][ar0 + 64] = a1n.z; As[nb][ac0 + 3][ar0 + 64] = a1n.w;
            *(float4*)&Bs[nb][br0][bc0]     = b0n;
            *(float4*)&Bs[nb][br0 + 8][bc0] = b1n;
        }
        __syncthreads();
    }

    // ---- epilogue ----
#pragma unroll
    for (int i = 0; i < 8; i++) {
        const int m = bm + ty * 8 + i;
#pragma unroll
        for (int j = 0; j < 8; j++) {
            const int n = bn + tx * 8 + j;
            float v = acc[i][j] + bias[n];
            const size_t co = (size_t)m * ldc + n;
            const size_t eo = (size_t)m * H_DIM + n;
            if (EPI == EPI_LIN) {
                C[co] = v;
            } else if (EPI == EPI_BELTA) {
                float bl = __expf(-fmaxf(v, 0.0f));
                C[co] = bl * ex1[eo];                       // spre = belta * state
            } else if (EPI == EPI_SIGU) {
                C[co] = 1.0f / (1.0f + __expf(-v));         // u
            } else if (EPI == EPI_SIGR) {
                float r = 1.0f / (1.0f + __expf(-v));
                C[co] = r * ex1[eo];                        // r * spre
            } else if (EPI == EPI_NEW) {
                float ns = tanhf(v);
                float u = ex1[eo];
                float sp = ex2[eo];
                C[co] = (1.0f - u) * sp + u * ns;           // new state
            }
        }
    }
}

extern "C" void kernel_launch(void* const* d_in, const int* in_sizes, int n_in,
                              void* d_out, int out_size)
{
    const float* z       = (const float*)d_in[0];
    const float* td      = (const float*)d_in[1];
    const float* W_belta = (const float*)d_in[2];
    const float* b_belta = (const float*)d_in[3];
    const float* W_z     = (const float*)d_in[4];
    const float* b_z     = (const float*)d_in[5];
    const float* W1      = (const float*)d_in[6];
    const float* b1      = (const float*)d_in[7];
    const float* W2      = (const float*)d_in[8];
    const float* b2      = (const float*)d_in[9];
    const float* W3      = (const float*)d_in[10];
    const float* b3      = (const float*)d_in[11];
    const float* W_out   = (const float*)d_in[12];
    const float* b_out   = (const float*)d_in[13];
    float* out = (float*)d_out;

    float *x0, *st, *sp, *u, *rs;
    cudaGetSymbolAddress((void**)&x0, g_x0);
    cudaGetSymbolAddress((void**)&st, g_state);
    cudaGetSymbolAddress((void**)&sp, g_spre);
    cudaGetSymbolAddress((void**)&u,  g_u);
    cudaGetSymbolAddress((void**)&rs, g_rs);

    // state must start at zero on EVERY launch (graph replay determinism)
    zero_kernel<<<(B_DIM * H_DIM + 1023) / 1024, 1024>>>(st, B_DIM * H_DIM);

    const dim3 blk(256);
    const dim3 gridH(H_DIM / BN, B_DIM / BM);   // (8, 32)
    const dim3 gridI(IN_DIM / BN, B_DIM / BM);  // (4, 32)
    const int ldo = SEQ_LEN * IN_DIM;

    // x0 = z @ W_z + b_z
    gemm_epi<EPI_LIN><<<gridI, blk>>>(z, ZDIM, ZDIM, nullptr, 0, 0,
                                      W_z, b_z, nullptr, nullptr,
                                      x0, IN_DIM, IN_DIM);

    for (int t = 0; t < SEQ_LEN; t++) {
        const float* xp = (t == 0) ? x0 : out + (size_t)(t - 1) * IN_DIM;
        const int ldx   = (t == 0) ? IN_DIM : ldo;

        // spre = exp(-relu(td_t @ W_belta + b)) * state
        gemm_epi<EPI_BELTA><<<gridH, blk>>>(td + (size_t)t * IN_DIM, ldo, IN_DIM,
                                            nullptr, 0, 0,
                                            W_belta, b_belta, st, nullptr,
                                            sp, H_DIM, H_DIM);
        // u = sigmoid([spre|x] @ W1 + b1)
        gemm_epi<EPI_SIGU><<<gridH, blk>>>(sp, H_DIM, H_DIM, xp, ldx, IN_DIM,
                                           W1, b1, nullptr, nullptr,
                                           u, H_DIM, H_DIM);
        // rs = sigmoid([spre|x] @ W2 + b2) * spre
        gemm_epi<EPI_SIGR><<<gridH, blk>>>(sp, H_DIM, H_DIM, xp, ldx, IN_DIM,
                                           W2, b2, sp, nullptr,
                                           rs, H_DIM, H_DIM);
        // state = (1-u)*spre + u*tanh([rs|x] @ W3 + b3)
        gemm_epi<EPI_NEW><<<gridH, blk>>>(rs, H_DIM, H_DIM, xp, ldx, IN_DIM,
                                          W3, b3, u, sp,
                                          st, H_DIM, H_DIM);
        // out_t = state @ W_out + b_out   (written strided into d_out[:, t, :])
        gemm_epi<EPI_LIN><<<gridI, blk>>>(st, H_DIM, H_DIM, nullptr, 0, 0,
                                          W_out, b_out, nullptr, nullptr,
                                          out + (size_t)t * IN_DIM, ldo, IN_DIM);
    }
}

// round 6
// speedup vs baseline: 2.0055x; 2.0055x over previous
#include <cuda_runtime.h>
#include <cuda_bf16.h>
#include <math.h>
#include <stdint.h>

#define B_DIM   4096
#define ZDIM    128
#define IN_DIM  512
#define H_DIM   1024
#define SEQ_LEN 12
#define CAT     (IN_DIM + H_DIM)
#define LDO     (SEQ_LEN * IN_DIM)

typedef __nv_bfloat16  bf16;
typedef __nv_bfloat162 bf162;

// ---------------- scratch (__device__ globals; no allocs allowed) -----------
__device__ float g_stf[B_DIM * H_DIM];
__device__ float g_spf[B_DIM * H_DIM];
__device__ float g_uf [B_DIM * H_DIM];

__device__ bf16 g_tdh[B_DIM * LDO],    g_tdl[B_DIM * LDO];
__device__ bf16 g_zh [B_DIM * ZDIM],   g_zl [B_DIM * ZDIM];
__device__ bf16 g_sph[B_DIM * H_DIM],  g_spl[B_DIM * H_DIM];
__device__ bf16 g_sth[B_DIM * H_DIM],  g_stl[B_DIM * H_DIM];
__device__ bf16 g_rsh[B_DIM * H_DIM],  g_rsl[B_DIM * H_DIM];
__device__ bf16 g_xh [B_DIM * IN_DIM], g_xl [B_DIM * IN_DIM];

// weights transposed to [N][K] bf16 hi/lo
__device__ bf16 g_W1h[H_DIM * CAT],    g_W1l[H_DIM * CAT];
__device__ bf16 g_W2h[H_DIM * CAT],    g_W2l[H_DIM * CAT];
__device__ bf16 g_W3h[H_DIM * CAT],    g_W3l[H_DIM * CAT];
__device__ bf16 g_Wbh[H_DIM * IN_DIM], g_Wbl[H_DIM * IN_DIM];
__device__ bf16 g_Woh[IN_DIM * H_DIM], g_Wol[IN_DIM * H_DIM];
__device__ bf16 g_Wzh[IN_DIM * ZDIM],  g_Wzl[IN_DIM * ZDIM];

enum { EPI_LIN = 0, EPI_BELTA = 1, EPI_SIGU = 2, EPI_SIGR = 3, EPI_NEW = 4 };

// ---------------- prep kernels ---------------------------------------------
__global__ void zero_kernel(float* __restrict__ p, int n) {
    int i = blockIdx.x * blockDim.x + threadIdx.x;
    if (i < n) p[i] = 0.0f;
}

// elementwise fp32 -> bf16 hi/lo split (contiguous)
__global__ void asplit(const float* __restrict__ X, int n4,
                       bf16* __restrict__ H, bf16* __restrict__ L) {
    int i = blockIdx.x * blockDim.x + threadIdx.x;
    if (i >= n4) return;
    float4 v = ((const float4*)X)[i];
    bf162 h0 = __floats2bfloat162_rn(v.x, v.y);
    bf162 h1 = __floats2bfloat162_rn(v.z, v.w);
    bf162 l0 = __floats2bfloat162_rn(v.x - __low2float(h0), v.y - __high2float(h0));
    bf162 l1 = __floats2bfloat162_rn(v.z - __low2float(h1), v.w - __high2float(h1));
    ((bf162*)H)[2 * i]     = h0;
    ((bf162*)H)[2 * i + 1] = h1;
    ((bf162*)L)[2 * i]     = l0;
    ((bf162*)L)[2 * i + 1] = l1;
}

// transpose + hi/lo split: W (K,N) row-major -> Th/Tl [N][K]
__global__ void wsplit(const float* __restrict__ W, int K, int N,
                       bf16* __restrict__ Th, bf16* __restrict__ Tl) {
    __shared__ float t[32][33];
    const int n0 = blockIdx.x * 32, k0 = blockIdx.y * 32;
    const int tx = threadIdx.x, ty = threadIdx.y;   // (32, 8)
#pragma unroll
    for (int j = 0; j < 32; j += 8)
        t[ty + j][tx] = W[(size_t)(k0 + ty + j) * N + (n0 + tx)];
    __syncthreads();
#pragma unroll
    for (int j = 0; j < 32; j += 8) {
        float v = t[tx][ty + j];
        bf16 h = __float2bfloat16_rn(v);
        float l = v - __bfloat162float(h);
        size_t o = (size_t)(n0 + ty + j) * K + (k0 + tx);
        Th[o] = h;
        Tl[o] = __float2bfloat16_rn(l);
    }
}

// ---------------- PTX primitives (sm_80-era: valid for plain sm_103) --------
__device__ __forceinline__ uint32_t smem_u32(const void* p) {
    uint32_t a;
    asm("{ .reg .u64 t; cvta.to.shared.u64 t, %1; cvt.u32.u64 %0, t; }" : "=r"(a) : "l"(p));
    return a;
}

#define CP16(dst, src) \
    asm volatile("cp.async.ca.shared.global [%0], [%1], 16;" :: "r"(dst), "l"(src) : "memory")
#define CPCOMMIT() asm volatile("cp.async.commit_group;" ::: "memory")
#define CPWAIT1()  asm volatile("cp.async.wait_group 1;"  ::: "memory")

#define LDSM4(r, a) \
    asm volatile("ldmatrix.sync.aligned.m8n8.x4.shared.b16 {%0,%1,%2,%3}, [%4];" \
        : "=r"((r)[0]), "=r"((r)[1]), "=r"((r)[2]), "=r"((r)[3]) : "r"(a))
#define LDSM2(r, a) \
    asm volatile("ldmatrix.sync.aligned.m8n8.x2.shared.b16 {%0,%1}, [%2];" \
        : "=r"((r)[0]), "=r"((r)[1]) : "r"(a))

#define MMA(c, a, b) \
    asm volatile("mma.sync.aligned.m16n8k16.row.col.f32.bf16.bf16.f32 " \
        "{%0,%1,%2,%3}, {%4,%5,%6,%7}, {%8,%9}, {%0,%1,%2,%3};" \
        : "+f"((c)[0]), "+f"((c)[1]), "+f"((c)[2]), "+f"((c)[3]) \
        : "r"((a)[0]), "r"((a)[1]), "r"((a)[2]), "r"((a)[3]), "r"((b)[0]), "r"((b)[1]))

// ---------------- HMMA GEMM with fused epilogue -----------------------------
// C = epi([A1|A2] @ W + bias); A given as bf16 hi/lo [M][K] rows; W as [N][K].
#define KC      32                   // K elems per chunk
#define AROW    40                   // padded halves per SMEM row (80B)
#define TILE_B  (128 * AROW * 2)     // 10240 B per tile
#define STAGE   (4 * TILE_B)         // Ahi, Alo, Bhi, Blo
#define SMEM_T  (2 * STAGE)          // 81920 B

template <int EPI>
__global__ __launch_bounds__(256, 2)
void tgemm(const bf16* __restrict__ Ah1, const bf16* __restrict__ Al1, int lda1, int K1,
           const bf16* __restrict__ Ah2, const bf16* __restrict__ Al2, int lda2, int K2,
           const bf16* __restrict__ Bh,  const bf16* __restrict__ Bl,
           const float* __restrict__ bias,
           const float* __restrict__ ex1, const float* __restrict__ ex2,
           float* __restrict__ Cf, int ldcf,
           bf16* __restrict__ Ch, bf16* __restrict__ Cl, int ldch)
{
    extern __shared__ __align__(128) char smem[];
    const uint32_t sb = smem_u32(smem);
    const int tid = threadIdx.x;
    const int bm = blockIdx.y * 128, bn = blockIdx.x * 128;
    const int Ktot = K1 + K2;
    const int KT = Ktot / KC;

    // --- async copy mapping: thread -> (row, 2 x 16B segments) ---
    const int cr = tid >> 1;
    const int cs = (tid & 1) * 2;

    auto issue = [&](int c, int s) {
        const int ks = c * KC;
        const bf16 *ah, *al;
        if (ks < K1) {
            ah = Ah1 + (size_t)(bm + cr) * lda1 + ks;
            al = Al1 + (size_t)(bm + cr) * lda1 + ks;
        } else {
            ah = Ah2 + (size_t)(bm + cr) * lda2 + (ks - K1);
            al = Al2 + (size_t)(bm + cr) * lda2 + (ks - K1);
        }
        const bf16* bh = Bh + (size_t)(bn + cr) * Ktot + ks;
        const bf16* bl = Bl + (size_t)(bn + cr) * Ktot + ks;
        const uint32_t base = sb + (uint32_t)s * STAGE + (uint32_t)cr * (AROW * 2);
#pragma unroll
        for (int g = 0; g < 2; g++) {
            const int seg = cs + g;
            const uint32_t off = (uint32_t)seg * 16u;
            CP16(base + 0 * TILE_B + off, ah + seg * 8);
            CP16(base + 1 * TILE_B + off, al + seg * 8);
            CP16(base + 2 * TILE_B + off, bh + seg * 8);
            CP16(base + 3 * TILE_B + off, bl + seg * 8);
        }
    };

    // --- mma fragment mapping ---
    const int warp = tid >> 5, lane = tid & 31;
    const int wm = (warp & 3) * 32;            // 4 warps along M
    const int wn = (warp >> 2) * 64;           // 2 warps along N
    const int lr  = lane & 7;
    const int ra  = ((lane >> 3) & 1) * 8;     // A: +8 rows for mats 1,3
    const int ka  = ((lane >> 4) & 1) * 8;     // A: +8 k for mats 2,3
    const int kb  = ((lane >> 3) & 1) * 8;     // B: +8 k for mat 1
    const uint32_t aBase = (uint32_t)(wm + lr + ra) * (AROW * 2) + (uint32_t)ka * 2;
    const uint32_t bBase = (uint32_t)(wn + lr) * (AROW * 2) + (uint32_t)kb * 2;

    float acc[2][8][4];
#pragma unroll
    for (int mi = 0; mi < 2; mi++)
#pragma unroll
        for (int j = 0; j < 8; j++)
#pragma unroll
            for (int q = 0; q < 4; q++) acc[mi][j][q] = 0.0f;

    // --- pipeline: 2-stage cp.async double buffer ---
    issue(0, 0); CPCOMMIT();
    issue(1, 1); CPCOMMIT();

    for (int c = 0; c < KT; c++) {
        CPWAIT1();
        __syncthreads();
        const uint32_t st = sb + (uint32_t)(c & 1) * STAGE;
#pragma unroll
        for (int k2 = 0; k2 < 2; k2++) {
            uint32_t ah[2][4], al[2][4];
#pragma unroll
            for (int mi = 0; mi < 2; mi++) {
                const uint32_t ao = st + aBase + (uint32_t)mi * (16 * AROW * 2) + (uint32_t)k2 * 32;
                LDSM4(ah[mi], ao);
                LDSM4(al[mi], ao + TILE_B);
            }
#pragma unroll
            for (int j = 0; j < 8; j++) {
                uint32_t bh[2], bl[2];
                const uint32_t bo = st + 2 * TILE_B + bBase + (uint32_t)j * (8 * AROW * 2)
                                    + (uint32_t)k2 * 32;
                LDSM2(bh, bo);
                LDSM2(bl, bo + TILE_B);
                MMA(acc[0][j], ah[0], bh);
                MMA(acc[1][j], ah[1], bh);
                MMA(acc[0][j], ah[0], bl);
                MMA(acc[1][j], ah[1], bl);
                MMA(acc[0][j], al[0], bh);
                MMA(acc[1][j], al[1], bh);
            }
        }
        __syncthreads();
        if (c + 2 < KT) issue(c + 2, c & 1);
        CPCOMMIT();
    }

    // --- epilogue ---
    const int r0 = bm + wm + (lane >> 2);
    const int c0 = bn + wn + 2 * (lane & 3);

    auto dopair = [&](int row, int col, float v0, float v1) {
        v0 += bias[col];
        v1 += bias[col + 1];
        if (EPI == EPI_BELTA) {
            float2 e = *(const float2*)(ex1 + (size_t)row * H_DIM + col);
            v0 = __expf(-fmaxf(v0, 0.0f)) * e.x;
            v1 = __expf(-fmaxf(v1, 0.0f)) * e.y;
        } else if (EPI == EPI_SIGU) {
            v0 = 1.0f / (1.0f + __expf(-v0));
            v1 = 1.0f / (1.0f + __expf(-v1));
        } else if (EPI == EPI_SIGR) {
            float2 e = *(const float2*)(ex1 + (size_t)row * H_DIM + col);
            v0 = e.x / (1.0f + __expf(-v0));
            v1 = e.y / (1.0f + __expf(-v1));
        } else if (EPI == EPI_NEW) {
            float2 eu = *(const float2*)(ex1 + (size_t)row * H_DIM + col);
            float2 es = *(const float2*)(ex2 + (size_t)row * H_DIM + col);
            v0 = (1.0f - eu.x) * es.x + eu.x * tanhf(v0);
            v1 = (1.0f - eu.y) * es.y + eu.y * tanhf(v1);
        }
        if (Cf) *(float2*)(Cf + (size_t)row * ldcf + col) = make_float2(v0, v1);
        if (Ch) {
            bf16 h0 = __float2bfloat16_rn(v0), h1 = __float2bfloat16_rn(v1);
            bf162 hh; hh.x = h0; hh.y = h1;
            bf162 ll;
            ll.x = __float2bfloat16_rn(v0 - __bfloat162float(h0));
            ll.y = __float2bfloat16_rn(v1 - __bfloat162float(h1));
            *(bf162*)(Ch + (size_t)row * ldch + col) = hh;
            *(bf162*)(Cl + (size_t)row * ldch + col) = ll;
        }
    };

#pragma unroll
    for (int mi = 0; mi < 2; mi++)
#pragma unroll
        for (int j = 0; j < 8; j++) {
            const int row = r0 + mi * 16;
            const int col = c0 + j * 8;
            dopair(row,     col, acc[mi][j][0], acc[mi][j][1]);
            dopair(row + 8, col, acc[mi][j][2], acc[mi][j][3]);
        }
}

// ---------------- host -------------------------------------------------------
extern "C" void kernel_launch(void* const* d_in, const int* in_sizes, int n_in,
                              void* d_out, int out_size)
{
    const float* z       = (const float*)d_in[0];
    const float* td      = (const float*)d_in[1];
    const float* W_belta = (const float*)d_in[2];
    const float* b_belta = (const float*)d_in[3];
    const float* W_z     = (const float*)d_in[4];
    const float* b_z     = (const float*)d_in[5];
    const float* W1      = (const float*)d_in[6];
    const float* b1      = (const float*)d_in[7];
    const float* W2      = (const float*)d_in[8];
    const float* b2      = (const float*)d_in[9];
    const float* W3      = (const float*)d_in[10];
    const float* b3      = (const float*)d_in[11];
    const float* W_out   = (const float*)d_in[12];
    const float* b_out   = (const float*)d_in[13];
    float* out = (float*)d_out;

    float *stf, *spf, *uf;
    cudaGetSymbolAddress((void**)&stf, g_stf);
    cudaGetSymbolAddress((void**)&spf, g_spf);
    cudaGetSymbolAddress((void**)&uf,  g_uf);

    bf16 *tdh, *tdl, *zh, *zl, *sph, *spl, *sth, *stl, *rsh, *rsl, *xh, *xl;
    cudaGetSymbolAddress((void**)&tdh, g_tdh); cudaGetSymbolAddress((void**)&tdl, g_tdl);
    cudaGetSymbolAddress((void**)&zh,  g_zh);  cudaGetSymbolAddress((void**)&zl,  g_zl);
    cudaGetSymbolAddress((void**)&sph, g_sph); cudaGetSymbolAddress((void**)&spl, g_spl);
    cudaGetSymbolAddress((void**)&sth, g_sth); cudaGetSymbolAddress((void**)&stl, g_stl);
    cudaGetSymbolAddress((void**)&rsh, g_rsh); cudaGetSymbolAddress((void**)&rsl, g_rsl);
    cudaGetSymbolAddress((void**)&xh,  g_xh);  cudaGetSymbolAddress((void**)&xl,  g_xl);

    bf16 *W1h, *W1l, *W2h, *W2l, *W3h, *W3l, *Wbh, *Wbl, *Woh, *Wol, *Wzh, *Wzl;
    cudaGetSymbolAddress((void**)&W1h, g_W1h); cudaGetSymbolAddress((void**)&W1l, g_W1l);
    cudaGetSymbolAddress((void**)&W2h, g_W2h); cudaGetSymbolAddress((void**)&W2l, g_W2l);
    cudaGetSymbolAddress((void**)&W3h, g_W3h); cudaGetSymbolAddress((void**)&W3l, g_W3l);
    cudaGetSymbolAddress((void**)&Wbh, g_Wbh); cudaGetSymbolAddress((void**)&Wbl, g_Wbl);
    cudaGetSymbolAddress((void**)&Woh, g_Woh); cudaGetSymbolAddress((void**)&Wol, g_Wol);
    cudaGetSymbolAddress((void**)&Wzh, g_Wzh); cudaGetSymbolAddress((void**)&Wzl, g_Wzl);

    cudaFuncSetAttribute(tgemm<EPI_LIN>,   cudaFuncAttributeMaxDynamicSharedMemorySize, SMEM_T);
    cudaFuncSetAttribute(tgemm<EPI_BELTA>, cudaFuncAttributeMaxDynamicSharedMemorySize, SMEM_T);
    cudaFuncSetAttribute(tgemm<EPI_SIGU>,  cudaFuncAttributeMaxDynamicSharedMemorySize, SMEM_T);
    cudaFuncSetAttribute(tgemm<EPI_SIGR>,  cudaFuncAttributeMaxDynamicSharedMemorySize, SMEM_T);
    cudaFuncSetAttribute(tgemm<EPI_NEW>,   cudaFuncAttributeMaxDynamicSharedMemorySize, SMEM_T);

    // ---- per-launch prep (deterministic for graph replay) ----
    zero_kernel<<<(B_DIM * H_DIM + 1023) / 1024, 1024>>>(stf, B_DIM * H_DIM);
    {
        int n4 = (B_DIM * LDO) / 4;
        asplit<<<(n4 + 255) / 256, 256>>>(td, n4, tdh, tdl);
        n4 = (B_DIM * ZDIM) / 4;
        asplit<<<(n4 + 255) / 256, 256>>>(z, n4, zh, zl);
    }
    dim3 tb(32, 8);
    wsplit<<<dim3(H_DIM / 32, CAT / 32),    tb>>>(W1,      CAT,    H_DIM,  W1h, W1l);
    wsplit<<<dim3(H_DIM / 32, CAT / 32),    tb>>>(W2,      CAT,    H_DIM,  W2h, W2l);
    wsplit<<<dim3(H_DIM / 32, CAT / 32),    tb>>>(W3,      CAT,    H_DIM,  W3h, W3l);
    wsplit<<<dim3(H_DIM / 32, IN_DIM / 32), tb>>>(W_belta, IN_DIM, H_DIM,  Wbh, Wbl);
    wsplit<<<dim3(IN_DIM / 32, H_DIM / 32), tb>>>(W_out,   H_DIM,  IN_DIM, Woh, Wol);
    wsplit<<<dim3(IN_DIM / 32, ZDIM / 32),  tb>>>(W_z,     ZDIM,   IN_DIM, Wzh, Wzl);

    const dim3 blk(256);
    const dim3 gridH(H_DIM / 128, B_DIM / 128);    // (8, 32)
    const dim3 gridI(IN_DIM / 128, B_DIM / 128);   // (4, 32)

    // x0 = z @ W_z + b_z  -> hi/lo only
    tgemm<EPI_LIN><<<gridI, blk, SMEM_T>>>(zh, zl, ZDIM, ZDIM, nullptr, nullptr, 0, 0,
                                           Wzh, Wzl, b_z, nullptr, nullptr,
                                           nullptr, 0, xh, xl, IN_DIM);

    for (int t = 0; t < SEQ_LEN; t++) {
        // spre = exp(-relu(td_t @ W_belta + b)) * state   (fp32 + hi/lo)
        tgemm<EPI_BELTA><<<gridH, blk, SMEM_T>>>(tdh + (size_t)t * IN_DIM,
                                                 tdl + (size_t)t * IN_DIM, LDO, IN_DIM,
                                                 nullptr, nullptr, 0, 0,
                                                 Wbh, Wbl, b_belta, stf, nullptr,
                                                 spf, H_DIM, sph, spl, H_DIM);
        // u = sigmoid([spre|x] @ W1 + b1)                 (fp32 only)
        tgemm<EPI_SIGU><<<gridH, blk, SMEM_T>>>(sph, spl, H_DIM, H_DIM,
                                                xh, xl, IN_DIM, IN_DIM,
                                                W1h, W1l, b1, nullptr, nullptr,
                                                uf, H_DIM, nullptr, nullptr, 0);
        // rs = sigmoid([spre|x] @ W2 + b2) * spre         (hi/lo only)
        tgemm<EPI_SIGR><<<gridH, blk, SMEM_T>>>(sph, spl, H_DIM, H_DIM,
                                                xh, xl, IN_DIM, IN_DIM,
                                                W2h, W2l, b2, spf, nullptr,
                                                nullptr, 0, rsh, rsl, H_DIM);
        // state = (1-u)*spre + u*tanh([rs|x] @ W3 + b3)   (fp32 + hi/lo)
        tgemm<EPI_NEW><<<gridH, blk, SMEM_T>>>(rsh, rsl, H_DIM, H_DIM,
                                               xh, xl, IN_DIM, IN_DIM,
                                               W3h, W3l, b3, uf, spf,
                                               stf, H_DIM, sth, stl, H_DIM);
        // out_t = state @ W_out + b_out   (fp32 strided into d_out + hi/lo x feedback)
        tgemm<EPI_LIN><<<gridI, blk, SMEM_T>>>(sth, stl, H_DIM, H_DIM,
                                               nullptr, nullptr, 0, 0,
                                               Woh, Wol, b_out, nullptr, nullptr,
                                               out + (size_t)t * IN_DIM, LDO,
                                               xh, xl, IN_DIM);
    }
}

// round 7
// speedup vs baseline: 2.9285x; 1.4602x over previous
#include <cuda_runtime.h>
#include <cuda_fp16.h>
#include <math.h>
#include <stdint.h>

#define B_DIM   4096
#define ZDIM    128
#define IN_DIM  512
#define H_DIM   1024
#define SEQ_LEN 12
#define CAT     (IN_DIM + H_DIM)
#define LDO     (SEQ_LEN * IN_DIM)
#define N12     (2 * H_DIM)

typedef __half  f16;
typedef __half2 f162;

// ---------------- scratch (__device__ globals; no allocs allowed) -----------
__device__ float g_stf[B_DIM * H_DIM];
__device__ float g_spf[B_DIM * H_DIM];
__device__ float g_uf [B_DIM * H_DIM];

__device__ f16 g_tdh[B_DIM * LDO],    g_tdl[B_DIM * LDO];
__device__ f16 g_zh [B_DIM * ZDIM],   g_zl [B_DIM * ZDIM];
__device__ f16 g_sph[B_DIM * H_DIM],  g_spl[B_DIM * H_DIM];
__device__ f16 g_sth[B_DIM * H_DIM],  g_stl[B_DIM * H_DIM];
__device__ f16 g_rsh[B_DIM * H_DIM],  g_rsl[B_DIM * H_DIM];
__device__ f16 g_xh [B_DIM * IN_DIM], g_xl [B_DIM * IN_DIM];

// weights transposed to [N][K] fp16 (hi only — 2-term scheme)
__device__ f16 g_W12h[N12 * CAT];          // W1 rows then W2 rows
__device__ f16 g_W3h [H_DIM * CAT];
__device__ f16 g_Wbh [H_DIM * IN_DIM];
__device__ f16 g_Woh [IN_DIM * H_DIM];
__device__ f16 g_Wzh [IN_DIM * ZDIM];

enum { EPI_LIN = 0, EPI_BELTA = 1, EPI_SIGUR = 2, EPI_NEW = 3 };

// ---------------- prep kernels ---------------------------------------------
__global__ void zero_kernel(float* __restrict__ p, int n) {
    int i = blockIdx.x * blockDim.x + threadIdx.x;
    if (i < n) p[i] = 0.0f;
}

// fp32 -> fp16 hi/lo split (contiguous)
__global__ void asplit(const float* __restrict__ X, int n4,
                       f16* __restrict__ H, f16* __restrict__ L) {
    int i = blockIdx.x * blockDim.x + threadIdx.x;
    if (i >= n4) return;
    float4 v = ((const float4*)X)[i];
    f16 h0 = __float2half_rn(v.x), h1 = __float2half_rn(v.y);
    f16 h2 = __float2half_rn(v.z), h3 = __float2half_rn(v.w);
    f162 H0; H0.x = h0; H0.y = h1;
    f162 H1; H1.x = h2; H1.y = h3;
    f162 L0, L1;
    L0.x = __float2half_rn(v.x - __half2float(h0));
    L0.y = __float2half_rn(v.y - __half2float(h1));
    L1.x = __float2half_rn(v.z - __half2float(h2));
    L1.y = __float2half_rn(v.w - __half2float(h3));
    ((f162*)H)[2 * i] = H0; ((f162*)H)[2 * i + 1] = H1;
    ((f162*)L)[2 * i] = L0; ((f162*)L)[2 * i + 1] = L1;
}

// transpose + fp16 round: W (K,N) row-major -> Th [N][K]
__global__ void whalf(const float* __restrict__ W, int K, int N,
                      f16* __restrict__ Th) {
    __shared__ float t[32][33];
    const int n0 = blockIdx.x * 32, k0 = blockIdx.y * 32;
    const int tx = threadIdx.x, ty = threadIdx.y;   // (32, 8)
#pragma unroll
    for (int j = 0; j < 32; j += 8)
        t[ty + j][tx] = W[(size_t)(k0 + ty + j) * N + (n0 + tx)];
    __syncthreads();
#pragma unroll
    for (int j = 0; j < 32; j += 8)
        Th[(size_t)(n0 + ty + j) * K + (k0 + tx)] = __float2half_rn(t[tx][ty + j]);
}

// ---------------- PTX primitives --------------------------------------------
__device__ __forceinline__ uint32_t smem_u32(const void* p) {
    uint32_t a;
    asm("{ .reg .u64 t; cvta.to.shared.u64 t, %1; cvt.u32.u64 %0, t; }" : "=r"(a) : "l"(p));
    return a;
}

#define CP16(dst, src) \
    asm volatile("cp.async.ca.shared.global [%0], [%1], 16;" :: "r"(dst), "l"(src) : "memory")
#define CPCOMMIT() asm volatile("cp.async.commit_group;" ::: "memory")
#define CPWAIT1()  asm volatile("cp.async.wait_group 1;"  ::: "memory")

#define LDSM4(r, a) \
    asm volatile("ldmatrix.sync.aligned.m8n8.x4.shared.b16 {%0,%1,%2,%3}, [%4];" \
        : "=r"((r)[0]), "=r"((r)[1]), "=r"((r)[2]), "=r"((r)[3]) : "r"(a))

#define MMA(c, a, b0, b1) \
    asm volatile("mma.sync.aligned.m16n8k16.row.col.f32.f16.f16.f32 " \
        "{%0,%1,%2,%3}, {%4,%5,%6,%7}, {%8,%9}, {%0,%1,%2,%3};" \
        : "+f"((c)[0]), "+f"((c)[1]), "+f"((c)[2]), "+f"((c)[3]) \
        : "r"((a)[0]), "r"((a)[1]), "r"((a)[2]), "r"((a)[3]), "r"(b0), "r"(b1))

// ---------------- HMMA GEMM with fused epilogue -----------------------------
// C = epi([A1|A2] @ W + bias); A as fp16 hi/lo [M][K]; W as fp16 [N][K].
#define KC      32
#define AROW80  80                       // padded row pitch in bytes (32 halfs + pad)
#define TILE_B  (128 * AROW80)           // 10240 B
#define STAGE   (3 * TILE_B)             // Ahi, Alo, Bhi = 30720 B
#define NSTG    3
#define SMEM_T  (NSTG * STAGE)           // 92160 B

template <int EPI>
__global__ __launch_bounds__(256, 2)
void tgemm(const f16* __restrict__ Ah1, const f16* __restrict__ Al1, int lda1, int K1,
           const f16* __restrict__ Ah2, const f16* __restrict__ Al2, int lda2, int K2,
           const f16* __restrict__ Bh,
           const float* __restrict__ bias, const float* __restrict__ bias2,
           const float* __restrict__ ex1, const float* __restrict__ ex2,
           float* __restrict__ Cf, int ldcf,
           f16* __restrict__ Ch, f16* __restrict__ Cl, int ldch)
{
    extern __shared__ __align__(128) char smem[];
    const uint32_t sb = smem_u32(smem);
    const int tid = threadIdx.x;
    const int bm = blockIdx.y * 128, bn = blockIdx.x * 128;
    const int Ktot = K1 + K2;
    const int KT = Ktot / KC;

    // --- async copy mapping: 256 threads, 3 tiles x 128 rows x 64B ---
    const int cr = tid >> 1;              // row 0..127
    const int cs = (tid & 1) * 2;         // segments {cs, cs+1} of 4

    auto issue = [&](int c, int s) {
        const int ks = c * KC;
        const f16 *ah, *al;
        if (ks < K1) {
            ah = Ah1 + (size_t)(bm + cr) * lda1 + ks;
            al = Al1 + (size_t)(bm + cr) * lda1 + ks;
        } else {
            ah = Ah2 + (size_t)(bm + cr) * lda2 + (ks - K1);
            al = Al2 + (size_t)(bm + cr) * lda2 + (ks - K1);
        }
        const f16* bh = Bh + (size_t)(bn + cr) * Ktot + ks;
        const uint32_t base = sb + (uint32_t)s * STAGE + (uint32_t)cr * AROW80;
#pragma unroll
        for (int g = 0; g < 2; g++) {
            const int seg = cs + g;
            const uint32_t off = (uint32_t)seg * 16u;
            CP16(base + 0 * TILE_B + off, ah + seg * 8);
            CP16(base + 1 * TILE_B + off, al + seg * 8);
            CP16(base + 2 * TILE_B + off, bh + seg * 8);
        }
    };

    // --- mma fragment mapping: 8 warps = 4(M) x 2(N), warp tile 32x64 ---
    const int warp = tid >> 5, lane = tid & 31;
    const int wm = (warp & 3) * 32;
    const int wn = (warp >> 2) * 64;
    const int lr = lane & 7;
    const uint32_t aBase = (uint32_t)(wm + lr + ((lane >> 3) & 1) * 8) * AROW80
                         + (uint32_t)(((lane >> 4) & 1) * 8) * 2;
    const uint32_t bBase = (uint32_t)(wn + lr + ((lane >> 4) & 1) * 8) * AROW80
                         + (uint32_t)(((lane >> 3) & 1) * 8) * 2;

    float acc[2][8][4];
#pragma unroll
    for (int mi = 0; mi < 2; mi++)
#pragma unroll
        for (int j = 0; j < 8; j++)
#pragma unroll
            for (int q = 0; q < 4; q++) acc[mi][j][q] = 0.0f;

    // --- 3-stage cp.async ring, one barrier per chunk ---
    issue(0, 0); CPCOMMIT();
    issue(1, 1); CPCOMMIT();

    for (int c = 0; c < KT; c++) {
        CPWAIT1();
        __syncthreads();
        if (c + 2 < KT) issue(c + 2, (c + 2) % NSTG);
        CPCOMMIT();
        const uint32_t st = sb + (uint32_t)(c % NSTG) * STAGE;
#pragma unroll
        for (int k2 = 0; k2 < 2; k2++) {
            uint32_t ah[2][4], al[2][4];
#pragma unroll
            for (int mi = 0; mi < 2; mi++) {
                const uint32_t ao = st + aBase + (uint32_t)mi * (16 * AROW80)
                                  + (uint32_t)k2 * 32;
                LDSM4(ah[mi], ao);
                LDSM4(al[mi], ao + TILE_B);
            }
#pragma unroll
            for (int jj = 0; jj < 4; jj++) {
                uint32_t b4[4];
                const uint32_t bo = st + 2 * TILE_B + bBase
                                  + (uint32_t)jj * (16 * AROW80) + (uint32_t)k2 * 32;
                LDSM4(b4, bo);
                MMA(acc[0][2 * jj],     ah[0], b4[0], b4[1]);
                MMA(acc[1][2 * jj],     ah[1], b4[0], b4[1]);
                MMA(acc[0][2 * jj],     al[0], b4[0], b4[1]);
                MMA(acc[1][2 * jj],     al[1], b4[0], b4[1]);
                MMA(acc[0][2 * jj + 1], ah[0], b4[2], b4[3]);
                MMA(acc[1][2 * jj + 1], ah[1], b4[2], b4[3]);
                MMA(acc[0][2 * jj + 1], al[0], b4[2], b4[3]);
                MMA(acc[1][2 * jj + 1], al[1], b4[2], b4[3]);
            }
        }
    }

    // --- epilogue ---
    const int r0 = bm + wm + (lane >> 2);
    const int c0 = bn + wn + 2 * (lane & 3);

    auto dopair = [&](int row, int col, float v0, float v1) {
        if (EPI == EPI_SIGUR) {
            if (col < H_DIM) {
                float2 bs = *(const float2*)(bias + col);
                v0 = 1.0f / (1.0f + __expf(-(v0 + bs.x)));
                v1 = 1.0f / (1.0f + __expf(-(v1 + bs.y)));
                *(float2*)(Cf + (size_t)row * ldcf + col) = make_float2(v0, v1);
            } else {
                const int cc = col - H_DIM;
                float2 bs = *(const float2*)(bias2 + cc);
                float2 e  = *(const float2*)(ex1 + (size_t)row * H_DIM + cc);
                v0 = e.x / (1.0f + __expf(-(v0 + bs.x)));
                v1 = e.y / (1.0f + __expf(-(v1 + bs.y)));
                f16 h0 = __float2half_rn(v0), h1 = __float2half_rn(v1);
                f162 hh; hh.x = h0; hh.y = h1;
                f162 ll;
                ll.x = __float2half_rn(v0 - __half2float(h0));
                ll.y = __float2half_rn(v1 - __half2float(h1));
                *(f162*)(Ch + (size_t)row * ldch + cc) = hh;
                *(f162*)(Cl + (size_t)row * ldch + cc) = ll;
            }
            return;
        }
        float2 bs = *(const float2*)(bias + col);
        v0 += bs.x; v1 += bs.y;
        if (EPI == EPI_BELTA) {
            float2 e = *(const float2*)(ex1 + (size_t)row * H_DIM + col);
            v0 = __expf(-fmaxf(v0, 0.0f)) * e.x;
            v1 = __expf(-fmaxf(v1, 0.0f)) * e.y;
        } else if (EPI == EPI_NEW) {
            float2 eu = *(const float2*)(ex1 + (size_t)row * H_DIM + col);
            float2 es = *(const float2*)(ex2 + (size_t)row * H_DIM + col);
            v0 = (1.0f - eu.x) * es.x + eu.x * tanhf(v0);
            v1 = (1.0f - eu.y) * es.y + eu.y * tanhf(v1);
        }
        if (Cf) *(float2*)(Cf + (size_t)row * ldcf + col) = make_float2(v0, v1);
        if (Ch) {
            f16 h0 = __float2half_rn(v0), h1 = __float2half_rn(v1);
            f162 hh; hh.x = h0; hh.y = h1;
            f162 ll;
            ll.x = __float2half_rn(v0 - __half2float(h0));
            ll.y = __float2half_rn(v1 - __half2float(h1));
            *(f162*)(Ch + (size_t)row * ldch + col) = hh;
            *(f162*)(Cl + (size_t)row * ldch + col) = ll;
        }
    };

#pragma unroll
    for (int mi = 0; mi < 2; mi++)
#pragma unroll
        for (int j = 0; j < 8; j++) {
            const int row = r0 + mi * 16;
            const int col = c0 + j * 8;
            dopair(row,     col, acc[mi][j][0], acc[mi][j][1]);
            dopair(row + 8, col, acc[mi][j][2], acc[mi][j][3]);
        }
}

// ---------------- host -------------------------------------------------------
extern "C" void kernel_launch(void* const* d_in, const int* in_sizes, int n_in,
                              void* d_out, int out_size)
{
    const float* z       = (const float*)d_in[0];
    const float* td      = (const float*)d_in[1];
    const float* W_belta = (const float*)d_in[2];
    const float* b_belta = (const float*)d_in[3];
    const float* W_z     = (const float*)d_in[4];
    const float* b_z     = (const float*)d_in[5];
    const float* W1      = (const float*)d_in[6];
    const float* b1      = (const float*)d_in[7];
    const float* W2      = (const float*)d_in[8];
    const float* b2      = (const float*)d_in[9];
    const float* W3      = (const float*)d_in[10];
    const float* b3      = (const float*)d_in[11];
    const float* W_out   = (const float*)d_in[12];
    const float* b_out   = (const float*)d_in[13];
    float* out = (float*)d_out;

    float *stf, *spf, *uf;
    cudaGetSymbolAddress((void**)&stf, g_stf);
    cudaGetSymbolAddress((void**)&spf, g_spf);
    cudaGetSymbolAddress((void**)&uf,  g_uf);

    f16 *tdh, *tdl, *zh, *zl, *sph, *spl, *sth, *stl, *rsh, *rsl, *xh, *xl;
    cudaGetSymbolAddress((void**)&tdh, g_tdh); cudaGetSymbolAddress((void**)&tdl, g_tdl);
    cudaGetSymbolAddress((void**)&zh,  g_zh);  cudaGetSymbolAddress((void**)&zl,  g_zl);
    cudaGetSymbolAddress((void**)&sph, g_sph); cudaGetSymbolAddress((void**)&spl, g_spl);
    cudaGetSymbolAddress((void**)&sth, g_sth); cudaGetSymbolAddress((void**)&stl, g_stl);
    cudaGetSymbolAddress((void**)&rsh, g_rsh); cudaGetSymbolAddress((void**)&rsl, g_rsl);
    cudaGetSymbolAddress((void**)&xh,  g_xh);  cudaGetSymbolAddress((void**)&xl,  g_xl);

    f16 *W12h, *W3h, *Wbh, *Woh, *Wzh;
    cudaGetSymbolAddress((void**)&W12h, g_W12h);
    cudaGetSymbolAddress((void**)&W3h,  g_W3h);
    cudaGetSymbolAddress((void**)&Wbh,  g_Wbh);
    cudaGetSymbolAddress((void**)&Woh,  g_Woh);
    cudaGetSymbolAddress((void**)&Wzh,  g_Wzh);

    cudaFuncSetAttribute(tgemm<EPI_LIN>,   cudaFuncAttributeMaxDynamicSharedMemorySize, SMEM_T);
    cudaFuncSetAttribute(tgemm<EPI_BELTA>, cudaFuncAttributeMaxDynamicSharedMemorySize, SMEM_T);
    cudaFuncSetAttribute(tgemm<EPI_SIGUR>, cudaFuncAttributeMaxDynamicSharedMemorySize, SMEM_T);
    cudaFuncSetAttribute(tgemm<EPI_NEW>,   cudaFuncAttributeMaxDynamicSharedMemorySize, SMEM_T);

    // ---- per-launch prep (deterministic for graph replay) ----
    zero_kernel<<<(B_DIM * H_DIM + 1023) / 1024, 1024>>>(stf, B_DIM * H_DIM);
    {
        int n4 = (B_DIM * LDO) / 4;
        asplit<<<(n4 + 255) / 256, 256>>>(td, n4, tdh, tdl);
        n4 = (B_DIM * ZDIM) / 4;
        asplit<<<(n4 + 255) / 256, 256>>>(z, n4, zh, zl);
    }
    dim3 tb(32, 8);
    whalf<<<dim3(H_DIM / 32, CAT / 32),    tb>>>(W1,      CAT,    H_DIM,  W12h);
    whalf<<<dim3(H_DIM / 32, CAT / 32),    tb>>>(W2,      CAT,    H_DIM,  W12h + (size_t)H_DIM * CAT);
    whalf<<<dim3(H_DIM / 32, CAT / 32),    tb>>>(W3,      CAT,    H_DIM,  W3h);
    whalf<<<dim3(H_DIM / 32, IN_DIM / 32), tb>>>(W_belta, IN_DIM, H_DIM,  Wbh);
    whalf<<<dim3(IN_DIM / 32, H_DIM / 32), tb>>>(W_out,   H_DIM,  IN_DIM, Woh);
    whalf<<<dim3(IN_DIM / 32, ZDIM / 32),  tb>>>(W_z,     ZDIM,   IN_DIM, Wzh);

    const dim3 blk(256);
    const dim3 gridH (H_DIM / 128,  B_DIM / 128);   // (8, 32)
    const dim3 gridH2(N12 / 128,    B_DIM / 128);   // (16, 32)
    const dim3 gridI (IN_DIM / 128, B_DIM / 128);   // (4, 32)

    // x0 = z @ W_z + b_z  -> x hi/lo only
    tgemm<EPI_LIN><<<gridI, blk, SMEM_T>>>(zh, zl, ZDIM, ZDIM, nullptr, nullptr, 0, 0,
                                           Wzh, b_z, nullptr, nullptr, nullptr,
                                           nullptr, 0, xh, xl, IN_DIM);

    for (int t = 0; t < SEQ_LEN; t++) {
        // spre = exp(-relu(td_t @ W_belta + b)) * state   (fp32 + hi/lo)
        tgemm<EPI_BELTA><<<gridH, blk, SMEM_T>>>(tdh + (size_t)t * IN_DIM,
                                                 tdl + (size_t)t * IN_DIM, LDO, IN_DIM,
                                                 nullptr, nullptr, 0, 0,
                                                 Wbh, b_belta, nullptr, stf, nullptr,
                                                 spf, H_DIM, sph, spl, H_DIM);
        // fused: u = sig([spre|x]W1+b1) -> uf ;  rs = sig([spre|x]W2+b2)*spre -> hi/lo
        tgemm<EPI_SIGUR><<<gridH2, blk, SMEM_T>>>(sph, spl, H_DIM, H_DIM,
                                                  xh, xl, IN_DIM, IN_DIM,
                                                  W12h, b1, b2, spf, nullptr,
                                                  uf, H_DIM, rsh, rsl, H_DIM);
        // state = (1-u)*spre + u*tanh([rs|x] @ W3 + b3)   (fp32 + hi/lo)
        tgemm<EPI_NEW><<<gridH, blk, SMEM_T>>>(rsh, rsl, H_DIM, H_DIM,
                                               xh, xl, IN_DIM, IN_DIM,
                                               W3h, b3, nullptr, uf, spf,
                                               stf, H_DIM, sth, stl, H_DIM);
        // out_t = state @ W_out + b_out  (fp32 strided into d_out + x hi/lo feedback)
        tgemm<EPI_LIN><<<gridI, blk, SMEM_T>>>(sth, stl, H_DIM, H_DIM,
                                               nullptr, nullptr, 0, 0,
                                               Woh, b_out, nullptr, nullptr, nullptr,
                                               out + (size_t)t * IN_DIM, LDO,
                                               xh, xl, IN_DIM);
    }
}